// round 14
// baseline (speedup 1.0000x reference)
#include <cuda_runtime.h>
#include <cuda_bf16.h>
#include <math.h>

typedef unsigned long long ull;
typedef unsigned int u32;
typedef unsigned short u16;

#define Mdim 2048
#define Ndim 256
#define Kdim 256
#define ITERS 1000
#define NS_ITERS 10
#define WCOLS 8            // padded cols per cluster (4 real)
#define WSTRIDE 136        // per-column ushort stride (conflict-free)

// ---- dynamic SMEM layout (bytes) ----
#define OFF_WX   0
#define OFF_W    16                       // [3][WCOLS*WSTRIDE] u16 = 6528
#define OFF_PB   6544                     // [2][256] float4 = 8192
#define OFF_ALO  14736                    // [8][2][8][32] uint4 = 65536
#define SMEM_TOT 80272

// ---------------- scratch (allocation-free rule) ----------------
__device__ float g_G[Ndim * Ndim];
__device__ float g_Atb[Ndim * Kdim];
__device__ float g_X0[Ndim * Ndim];
__device__ float g_X1[Ndim * Ndim];
__device__ float g_Y[Ndim * Ndim];
__device__ float g_a[1];

// ---------------- prologue kernels (validated) ----------------
__global__ void atx_kernel(const float* __restrict__ A, const float* __restrict__ X,
                           float* __restrict__ C, const float* __restrict__ rho_p,
                           int addDiag)
{
    __shared__ float As[32][33];
    __shared__ float Xs[32][33];
    const int tx = threadIdx.x, ty = threadIdx.y;
    const int i0 = blockIdx.x * 32, j0 = blockIdx.y * 32;
    const int m0 = blockIdx.z * (Mdim / 4);
    float acc = 0.f;
    for (int mt = m0; mt < m0 + Mdim / 4; mt += 32) {
        As[ty][tx] = A[(mt + ty) * Ndim + i0 + tx];
        Xs[ty][tx] = X[(mt + ty) * Kdim + j0 + tx];
        __syncthreads();
#pragma unroll
        for (int mm = 0; mm < 32; mm++)
            acc = fmaf(As[mm][ty], Xs[mm][tx], acc);
        __syncthreads();
    }
    const int i = i0 + ty, j = j0 + tx;
    if (addDiag && i == j && blockIdx.z == 0) acc += fabsf(rho_p[0]) + 1e-10f;
    atomicAdd(&C[i * Kdim + j], acc);
}

__global__ void norm_kernel(const float* __restrict__ G, float* __restrict__ a_out)
{
    __shared__ float red[256];
    const int t = threadIdx.x;
    float s = 0.f;
    for (int j = 0; j < Ndim; j++) s += fabsf(G[j * Ndim + t]);
    red[t] = s;
    __syncthreads();
    for (int off = 128; off > 0; off >>= 1) {
        if (t < off) red[t] = fmaxf(red[t], red[t + off]);
        __syncthreads();
    }
    if (t == 0) a_out[0] = 1.0f / red[0];
}

__global__ void init_x_kernel(float* __restrict__ X, const float* __restrict__ a_p)
{
    const int idx = blockIdx.x * blockDim.x + threadIdx.x;
    const int i = idx >> 8, j = idx & 255;
    X[idx] = (i == j) ? a_p[0] : 0.f;
}

__global__ void gemm256_kernel(const float* __restrict__ A, const float* __restrict__ B,
                               float* __restrict__ C, int ns_mode)
{
    __shared__ float As[32][33];
    __shared__ float Bs[32][33];
    const int tx = threadIdx.x, ty = threadIdx.y;
    const int i = blockIdx.y * 32 + ty, j = blockIdx.x * 32 + tx;
    float acc = 0.f;
    for (int kt = 0; kt < Ndim; kt += 32) {
        As[ty][tx] = A[i * Ndim + kt + tx];
        Bs[ty][tx] = B[(kt + ty) * Ndim + j];
        __syncthreads();
#pragma unroll
        for (int mm = 0; mm < 32; mm++)
            acc = fmaf(As[ty][mm], Bs[mm][tx], acc);
        __syncthreads();
    }
    C[i * Ndim + j] = ns_mode ? fmaf(2.f, A[i * Ndim + j], -acc) : acc;
}

// ---------------- helpers ----------------
__device__ __forceinline__ u32 smem_u32(const void* p) {
    u32 a; asm("{ .reg .u64 t; cvta.to.shared.u64 t, %1; cvt.u32.u64 %0, t; }"
               : "=r"(a) : "l"(p));
    return a;
}
__device__ __forceinline__ u32 ctarank() {
    u32 r; asm("mov.u32 %0, %%cluster_ctarank;" : "=r"(r)); return r;
}
__device__ __forceinline__ u32 mapa_peer(u32 local, u32 rank) {
    u32 r; asm("mapa.shared::cluster.u32 %0, %1, %2;" : "=r"(r) : "r"(local), "r"(rank));
    return r;
}
__device__ __forceinline__ u16 bfb(float v) {
    __nv_bfloat16 h = __float2bfloat16(v);
    return __bfloat16_as_ushort(h);
}
__device__ __forceinline__ float bff(u16 b) {
    return __bfloat162float(__ushort_as_bfloat16(b));
}
// 3-level split of a pair (va, vb) -> packed u32 per level (va in low half)
__device__ __forceinline__ void split3_pack(float va, float vb,
                                            u32& ph, u32& pm, u32& pl) {
    const u16 ha = bfb(va), hb = bfb(vb);
    const float ra = va - bff(ha), rb = vb - bff(hb);
    const u16 ma = bfb(ra), mb = bfb(rb);
    const float sa = ra - bff(ma), sb = rb - bff(mb);
    const u16 la = bfb(sa), lb = bfb(sb);
    ph = (u32)ha | ((u32)hb << 16);
    pm = (u32)ma | ((u32)mb << 16);
    pl = (u32)la | ((u32)lb << 16);
}
__device__ __forceinline__ void mma16816(float* d, const u32* a, u32 b0, u32 b1) {
    asm volatile(
        "mma.sync.aligned.m16n8k16.row.col.f32.bf16.bf16.f32 "
        "{%0,%1,%2,%3}, {%4,%5,%6,%7}, {%8,%9}, {%0,%1,%2,%3};"
        : "+f"(d[0]), "+f"(d[1]), "+f"(d[2]), "+f"(d[3])
        : "r"(a[0]), "r"(a[1]), "r"(a[2]), "r"(a[3]), "r"(b0), "r"(b1));
}
#define BAR_WAIT_CL(bar, par) do {                                              \
    u32 _d = 0;                                                                 \
    while (!_d) {                                                               \
        asm volatile("{\n\t.reg .pred p;\n\t"                                   \
            "mbarrier.try_wait.parity.acquire.cluster.shared::cta.b64 p, [%1], %2, 0x989680;\n\t" \
            "selp.b32 %0, 1, 0, p;\n\t}"                                        \
            : "=r"(_d) : "r"(bar), "r"(par) : "memory");                        \
    } } while (0)

// ---------------------------------------------------------------------------
// HMMA ADMM, 3-level bf16 split, MEMORY-ORDERING FIX.
// R10-R13 all sat at rel_err ~1.1-1.3e-3 regardless of split precision AND
// of the intra-CTA barrier fix -> the stale data was the PEER PARTIAL: the
// exchange used plain mbarrier.arrive (sem=release, scope=CTA). A CTA-scope
// release does not synchronize-with the other CTA's cluster-scope acquire,
// so the waiter could read the PREVIOUS iteration's partial from pbuf
// (off by the per-iteration delta ~1e-3 -- exactly the observed error).
// Fix: mbarrier.arrive.release.CLUSTER.shared::cluster.
// ---------------------------------------------------------------------------
__global__ void __launch_bounds__(256, 1) __cluster_dims__(2, 1, 1)
admm_mma_kernel(const float* __restrict__ Minv, const float* __restrict__ Atb,
                const float* __restrict__ rho_p, const float* __restrict__ lam_p,
                float* __restrict__ out)
{
    extern __shared__ char smc[];
    u16*   wsm  = (u16*)(smc + OFF_W);          // [lev][col*136 + j]
    float4* pb  = (float4*)(smc + OFF_PB);      // [2][256]
    uint4* aloV = (uint4*)(smc + OFF_ALO);      // [warp][mt][kt][lane]

    const int tid  = threadIdx.x;
    const int warp = tid >> 5;
    const int lane = tid & 31;
    const u32 rank = ctarank();
    const int rsub = lane >> 2;
    const int kq   = lane & 3;
    const int n0   = 2 * kq;
    const int c0   = (blockIdx.x >> 1) * 4;
    const int real = (n0 < 4);

    const float rho = fabsf(rho_p[0]) + 1e-10f;
    const float tau = fabsf(lam_p[0]) / rho;

    if (tid == 0)
        asm volatile("mbarrier.init.shared.b64 [%0], %1;"
                     :: "r"(smem_u32(smc + OFF_WX)), "r"(256) : "memory");

    // zero all 3 w levels (padding cols stay 0)
    for (int i = tid; i < 3 * WCOLS * WSTRIDE / 2; i += 256)
        ((u32*)wsm)[i] = 0u;

    // ---- A fragments: hi/mid in regs, lo into SMEM slots ----
    u32 afr_h[2][8][4], afr_m[2][8][4];
#pragma unroll
    for (int mt = 0; mt < 2; mt++) {
        const int m0 = 128 * mt + 16 * warp + rsub;
#pragma unroll
        for (int kt = 0; kt < 8; kt++) {
            const int kg = 128 * (int)rank + 16 * kt + 2 * kq;
            uint4 lo4;
            split3_pack(__ldg(Minv + m0 * Ndim + kg),
                        __ldg(Minv + m0 * Ndim + kg + 1),
                        afr_h[mt][kt][0], afr_m[mt][kt][0], lo4.x);
            split3_pack(__ldg(Minv + (m0 + 8) * Ndim + kg),
                        __ldg(Minv + (m0 + 8) * Ndim + kg + 1),
                        afr_h[mt][kt][1], afr_m[mt][kt][1], lo4.y);
            split3_pack(__ldg(Minv + m0 * Ndim + kg + 8),
                        __ldg(Minv + m0 * Ndim + kg + 9),
                        afr_h[mt][kt][2], afr_m[mt][kt][2], lo4.z);
            split3_pack(__ldg(Minv + (m0 + 8) * Ndim + kg + 8),
                        __ldg(Minv + (m0 + 8) * Ndim + kg + 9),
                        afr_h[mt][kt][3], afr_m[mt][kt][3], lo4.w);
            aloV[((warp * 2 + mt) * 8 + kt) * 32 + lane] = lo4;
        }
    }

    // ---- per-thread state: local tile rows, cols n0,n0+1 ----
    const int jl0 = 16 * warp + rsub;
    const int gr0 = 128 * (int)rank + jl0;
    float atb[4], uv[4], tp[4];
#pragma unroll
    for (int i = 0; i < 4; i++) {
        const int grow = gr0 + ((i >> 1) ? 8 : 0);
        atb[i] = real ? __ldg(Atb + grow * Kdim + c0 + n0 + (i & 1)) : 0.f;
        uv[i] = 0.f; tp[i] = 0.f;
    }
    int woff[4];
#pragma unroll
    for (int i = 0; i < 4; i++)
        woff[i] = (n0 + (i & 1)) * WSTRIDE + jl0 + ((i >> 1) ? 8 : 0);
    __syncthreads();   // zero-fill done before initial w stores
#pragma unroll
    for (int i = 0; i < 4; i++) {     // initial w = Atb, 3-level split
        const float v = atb[i];
        const u16 h = bfb(v);
        const float r = v - bff(h);
        const u16 m = bfb(r);
        const u16 l = bfb(r - bff(m));
        wsm[woff[i]]                       = h;
        wsm[WCOLS * WSTRIDE + woff[i]]     = m;
        wsm[2 * WCOLS * WSTRIDE + woff[i]] = l;
    }

    // B-frag load pointers per level: w[col=rsub][k0=2kq]
    const u32* wh = (const u32*)&wsm[rsub * WSTRIDE + 2 * kq];
    const u32* wm = (const u32*)&wsm[WCOLS * WSTRIDE + rsub * WSTRIDE + 2 * kq];
    const u32* wl = (const u32*)&wsm[2 * WCOLS * WSTRIDE + rsub * WSTRIDE + 2 * kq];

    // exchange plumbing
    const u32 peer = 1u - rank;
    const u32 peer_wx = mapa_peer(smem_u32(smc + OFF_WX), peer);
    u32 my_pb[2], peer_pb[2];
#pragma unroll
    for (int p = 0; p < 2; p++) {
        my_pb[p]   = smem_u32(&pb[p * 256 + tid]);
        peer_pb[p] = mapa_peer(my_pb[p], peer);
    }
    const uint4* al0p = &aloV[((warp * 2 + 0) * 8) * 32 + lane];
    const uint4* al1p = &aloV[((warp * 2 + 1) * 8) * 32 + lane];

    __syncthreads();
    asm volatile("barrier.cluster.arrive.aligned;" ::: "memory");
    asm volatile("barrier.cluster.wait.aligned;"   ::: "memory");

    // ---------------- main loop ----------------
    for (int it = 0; it < ITERS; ++it) {
        const u32 par = (u32)(it & 1);
        __syncthreads();   // epilogue w-stores of prev iter before MMA reads

        float acc0[4] = {0.f, 0.f, 0.f, 0.f};
        float acc1[4] = {0.f, 0.f, 0.f, 0.f};
#pragma unroll
        for (int kt = 0; kt < 8; kt++) {
            const u32 bh0 = wh[8 * kt], bh1 = wh[8 * kt + 4];
            const u32 bm0 = wm[8 * kt], bm1 = wm[8 * kt + 4];
            const u32 bl0 = wl[8 * kt], bl1 = wl[8 * kt + 4];
            const uint4 al0 = al0p[kt * 32];
            const uint4 al1 = al1p[kt * 32];
            mma16816(acc0, afr_h[0][kt], bh0, bh1);      // ah*wh
            mma16816(acc1, afr_h[1][kt], bh0, bh1);
            mma16816(acc0, afr_h[0][kt], bm0, bm1);      // ah*wm
            mma16816(acc1, afr_h[1][kt], bm0, bm1);
            mma16816(acc0, afr_m[0][kt], bh0, bh1);      // am*wh
            mma16816(acc1, afr_m[1][kt], bh0, bh1);
            mma16816(acc0, afr_m[0][kt], bm0, bm1);      // am*wm
            mma16816(acc1, afr_m[1][kt], bm0, bm1);
            mma16816(acc0, afr_h[0][kt], bl0, bl1);      // ah*wl
            mma16816(acc1, afr_h[1][kt], bl0, bl1);
            mma16816(acc0, (const u32*)&al0, bh0, bh1);  // al*wh
            mma16816(acc1, (const u32*)&al1, bh0, bh1);
        }

        // all warps finish reading wsm before any thread stores new w below
        __syncthreads();

        // ship the peer-owned tile (mt = 1-rank), keep local (mt = rank)
        const float* sendq = rank ? acc0 : acc1;
        const float* keepq = rank ? acc1 : acc0;
        asm volatile("st.shared::cluster.v4.b32 [%0], {%1,%2,%3,%4};"
                     :: "r"(peer_pb[par]),
                        "r"(__float_as_uint(sendq[0])), "r"(__float_as_uint(sendq[1])),
                        "r"(__float_as_uint(sendq[2])), "r"(__float_as_uint(sendq[3]))
                     : "memory");
        // ORDERING FIX: cluster-scope release so the remote pbuf store above
        // is visible to the peer's cluster-scope acquire wait.
        asm volatile("mbarrier.arrive.release.cluster.shared::cluster.b64 _, [%0];"
                     :: "r"(peer_wx) : "memory");
        BAR_WAIT_CL(smem_u32(smc + OFF_WX), par);

        float4 pr;
        asm volatile("ld.shared.v4.f32 {%0,%1,%2,%3}, [%4];"
                     : "=f"(pr.x), "=f"(pr.y), "=f"(pr.z), "=f"(pr.w)
                     : "r"(my_pb[par]));
        tp[0] = keepq[0] + pr.x;
        tp[1] = keepq[1] + pr.y;
        tp[2] = keepq[2] + pr.z;
        tp[3] = keepq[3] + pr.w;

        // z/u update + 3-level w split/store
#pragma unroll
        for (int i = 0; i < 4; i++) {
            const float g = tp[i] + uv[i];
            float zn = fmaxf(g - tau, 0.f) + fminf(g + tau, 0.f);
            zn = fminf(fmaxf(zn, 0.f), 1.f);
            uv[i] += tp[i] - zn;
            const float w = fmaf(rho, zn - uv[i], atb[i]);
            const u16 h = bfb(w);
            const float r = w - bff(h);
            const u16 m = bfb(r);
            const u16 l = bfb(r - bff(m));
            wsm[woff[i]]                       = h;
            wsm[WCOLS * WSTRIDE + woff[i]]     = m;
            wsm[2 * WCOLS * WSTRIDE + woff[i]] = l;
        }
    }

    if (real) {
#pragma unroll
        for (int i = 0; i < 4; i++) {
            const int grow = gr0 + ((i >> 1) ? 8 : 0);
            out[grow * Kdim + c0 + n0 + (i & 1)] = tp[i];
        }
    }
    asm volatile("barrier.cluster.arrive.aligned;" ::: "memory");
    asm volatile("barrier.cluster.wait.aligned;"   ::: "memory");
}

// ---------------------------------------------------------------------------
extern "C" void kernel_launch(void* const* d_in, const int* in_sizes, int n_in,
                              void* d_out, int out_size)
{
    // metadata order: T, s_A, s_mic_data, rho_param, lam_param
    const float* s_A   = (const float*)d_in[1];
    const float* s_mic = (const float*)d_in[2];
    const float* rho_p = (const float*)d_in[3];
    const float* lam_p = (const float*)d_in[4];
    float* out = (float*)d_out;

    float *G, *Atb, *X0, *X1, *Y, *ap;
    cudaGetSymbolAddress((void**)&G,   g_G);
    cudaGetSymbolAddress((void**)&Atb, g_Atb);
    cudaGetSymbolAddress((void**)&X0,  g_X0);
    cudaGetSymbolAddress((void**)&X1,  g_X1);
    cudaGetSymbolAddress((void**)&Y,   g_Y);
    cudaGetSymbolAddress((void**)&ap,  g_a);

    cudaFuncSetAttribute(admm_mma_kernel,
                         cudaFuncAttributeMaxDynamicSharedMemorySize, SMEM_TOT);

    cudaMemsetAsync(G,   0, Ndim * Ndim * sizeof(float));
    cudaMemsetAsync(Atb, 0, Ndim * Kdim * sizeof(float));
    dim3 tb(32, 32);
    dim3 gbz(8, 8, 4);
    atx_kernel<<<gbz, tb>>>(s_A, s_A,   G,   rho_p, 1);
    atx_kernel<<<gbz, tb>>>(s_A, s_mic, Atb, rho_p, 0);

    // Newton-Schulz inverse (fp32): X <- 2X - X@(G@X)
    norm_kernel<<<1, 256>>>(G, ap);
    init_x_kernel<<<256, 256>>>(X0, ap);
    dim3 gb(8, 8);
    float* Xc = X0; float* Xn = X1;
    for (int i = 0; i < NS_ITERS; i++) {
        gemm256_kernel<<<gb, tb>>>(G,  Xc, Y,  0);
        gemm256_kernel<<<gb, tb>>>(Xc, Y,  Xn, 1);
        float* t = Xc; Xc = Xn; Xn = t;
    }

    admm_mma_kernel<<<128, 256, SMEM_TOT>>>(Xc, Atb, rho_p, lam_p, out);
}

// round 15
// speedup vs baseline: 1.2617x; 1.2617x over previous
#include <cuda_runtime.h>
#include <cuda_bf16.h>
#include <math.h>

typedef unsigned long long ull;
typedef unsigned int u32;
typedef unsigned short u16;

#define Mdim 2048
#define Ndim 256
#define Kdim 256
#define ITERS 1000
#define NS_ITERS 8
#define WCOLS 8            // padded cols per cluster (4 real)
#define WSTRIDE 136        // per-column ushort stride (conflict-free)
#define WLEV (WCOLS * WSTRIDE)        // u16 per level = 1088
#define WBUF (2 * WLEV)               // u16 per buffer (2 levels)

// ---------------- scratch (allocation-free rule) ----------------
__device__ float g_G[Ndim * Ndim];
__device__ float g_Atb[Ndim * Kdim];
__device__ float g_X0[Ndim * Ndim];
__device__ float g_X1[Ndim * Ndim];
__device__ float g_Y[Ndim * Ndim];
__device__ float g_a[1];

// ---------------- prologue kernels (validated) ----------------
__global__ void atx_kernel(const float* __restrict__ A, const float* __restrict__ X,
                           float* __restrict__ C, const float* __restrict__ rho_p,
                           int addDiag)
{
    __shared__ float As[32][33];
    __shared__ float Xs[32][33];
    const int tx = threadIdx.x, ty = threadIdx.y;
    const int i0 = blockIdx.x * 32, j0 = blockIdx.y * 32;
    const int m0 = blockIdx.z * (Mdim / 4);
    float acc = 0.f;
    for (int mt = m0; mt < m0 + Mdim / 4; mt += 32) {
        As[ty][tx] = A[(mt + ty) * Ndim + i0 + tx];
        Xs[ty][tx] = X[(mt + ty) * Kdim + j0 + tx];
        __syncthreads();
#pragma unroll
        for (int mm = 0; mm < 32; mm++)
            acc = fmaf(As[mm][ty], Xs[mm][tx], acc);
        __syncthreads();
    }
    const int i = i0 + ty, j = j0 + tx;
    if (addDiag && i == j && blockIdx.z == 0) acc += fabsf(rho_p[0]) + 1e-10f;
    atomicAdd(&C[i * Kdim + j], acc);
}

__global__ void norm_kernel(const float* __restrict__ G, float* __restrict__ a_out)
{
    __shared__ float red[256];
    const int t = threadIdx.x;
    float s = 0.f;
    for (int j = 0; j < Ndim; j++) s += fabsf(G[j * Ndim + t]);
    red[t] = s;
    __syncthreads();
    for (int off = 128; off > 0; off >>= 1) {
        if (t < off) red[t] = fmaxf(red[t], red[t + off]);
        __syncthreads();
    }
    if (t == 0) a_out[0] = 1.0f / red[0];
}

__global__ void init_x_kernel(float* __restrict__ X, const float* __restrict__ a_p)
{
    const int idx = blockIdx.x * blockDim.x + threadIdx.x;
    const int i = idx >> 8, j = idx & 255;
    X[idx] = (i == j) ? a_p[0] : 0.f;
}

__global__ void gemm256_kernel(const float* __restrict__ A, const float* __restrict__ B,
                               float* __restrict__ C, int ns_mode)
{
    __shared__ float As[32][33];
    __shared__ float Bs[32][33];
    const int tx = threadIdx.x, ty = threadIdx.y;
    const int i = blockIdx.y * 32 + ty, j = blockIdx.x * 32 + tx;
    float acc = 0.f;
    for (int kt = 0; kt < Ndim; kt += 32) {
        As[ty][tx] = A[i * Ndim + kt + tx];
        Bs[ty][tx] = B[(kt + ty) * Ndim + j];
        __syncthreads();
#pragma unroll
        for (int mm = 0; mm < 32; mm++)
            acc = fmaf(As[ty][mm], Bs[mm][tx], acc);
        __syncthreads();
    }
    C[i * Ndim + j] = ns_mode ? fmaf(2.f, A[i * Ndim + j], -acc) : acc;
}

// ---------------- helpers ----------------
__device__ __forceinline__ u32 smem_u32(const void* p) {
    u32 a; asm("{ .reg .u64 t; cvta.to.shared.u64 t, %1; cvt.u32.u64 %0, t; }"
               : "=r"(a) : "l"(p));
    return a;
}
__device__ __forceinline__ u32 ctarank() {
    u32 r; asm("mov.u32 %0, %%cluster_ctarank;" : "=r"(r)); return r;
}
__device__ __forceinline__ u32 mapa_peer(u32 local, u32 rank) {
    u32 r; asm("mapa.shared::cluster.u32 %0, %1, %2;" : "=r"(r) : "r"(local), "r"(rank));
    return r;
}
__device__ __forceinline__ u16 bfb(float v) {
    return __bfloat16_as_ushort(__float2bfloat16(v));
}
__device__ __forceinline__ float bff(u16 b) {
    return __bfloat162float(__ushort_as_bfloat16(b));
}
// 2-level split of a pair (va, vb) -> packed u32 per level (va in low half)
__device__ __forceinline__ void split2_pack(float va, float vb, u32& ph, u32& pl) {
    const u16 ha = bfb(va), hb = bfb(vb);
    const u16 la = bfb(va - bff(ha)), lb = bfb(vb - bff(hb));
    ph = (u32)ha | ((u32)hb << 16);
    pl = (u32)la | ((u32)lb << 16);
}
__device__ __forceinline__ void mma16816(float* d, const u32* a, u32 b0, u32 b1) {
    asm volatile(
        "mma.sync.aligned.m16n8k16.row.col.f32.bf16.bf16.f32 "
        "{%0,%1,%2,%3}, {%4,%5,%6,%7}, {%8,%9}, {%0,%1,%2,%3};"
        : "+f"(d[0]), "+f"(d[1]), "+f"(d[2]), "+f"(d[3])
        : "r"(a[0]), "r"(a[1]), "r"(a[2]), "r"(a[3]), "r"(b0), "r"(b1));
}
#define BAR_WAIT_CL(bar, par) do {                                              \
    u32 _d = 0;                                                                 \
    while (!_d) {                                                               \
        asm volatile("{\n\t.reg .pred p;\n\t"                                   \
            "mbarrier.try_wait.parity.acquire.cluster.shared::cta.b64 p, [%1], %2, 0x989680;\n\t" \
            "selp.b32 %0, 1, 0, p;\n\t}"                                        \
            : "=r"(_d) : "r"(bar), "r"(par) : "memory");                        \
    } } while (0)

// ---------------------------------------------------------------------------
// HMMA ADMM v2: 2-level bf16 split, ALL 4 product terms (hh,hl,lh,ll), with
// the R14 cluster-release ordering fix. Measured HMMA rt_SMSP ~= 16 on
// sm_100 -> MMA-throughput-bound; cutting 96 -> 64 MMA/warp/iter is a
// direct 1.5x on the bound. Precision: 2-level rep error ~2^-17/matvec,
// measured amplification ~11x -> ~1e-4 final (R10-13's ~1.1e-3 was the
// sync bug, not the split). w double-buffered -> ONE __syncthreads/iter.
// ---------------------------------------------------------------------------
__global__ void __launch_bounds__(256, 1) __cluster_dims__(2, 1, 1)
admm_mma_kernel(const float* __restrict__ Minv, const float* __restrict__ Atb,
                const float* __restrict__ rho_p, const float* __restrict__ lam_p,
                float* __restrict__ out)
{
    __shared__ u16    wsm[2 * WBUF];      // [buf][lev][col*WSTRIDE + j]
    __shared__ float4 pbuf[2][256];
    __shared__ ull    wxbar;

    const int tid  = threadIdx.x;
    const int warp = tid >> 5;
    const int lane = tid & 31;
    const u32 rank = ctarank();
    const int rsub = lane >> 2;
    const int kq   = lane & 3;
    const int n0   = 2 * kq;
    const int c0   = (blockIdx.x >> 1) * 4;
    const int real = (n0 < 4);

    const float rho = fabsf(rho_p[0]) + 1e-10f;
    const float tau = fabsf(lam_p[0]) / rho;

    if (tid == 0)
        asm volatile("mbarrier.init.shared.b64 [%0], %1;"
                     :: "r"(smem_u32(&wxbar)), "r"(256) : "memory");

    // zero both buffers, both levels (padding cols stay 0)
    for (int i = tid; i < WBUF; i += 256)
        ((u32*)wsm)[i] = 0u;

    // ---- A fragments (iteration-invariant, 2 levels in regs = 128 u32) ----
    u32 afr_h[2][8][4], afr_l[2][8][4];
#pragma unroll
    for (int mt = 0; mt < 2; mt++) {
        const int m0 = 128 * mt + 16 * warp + rsub;
#pragma unroll
        for (int kt = 0; kt < 8; kt++) {
            const int kg = 128 * (int)rank + 16 * kt + 2 * kq;
            split2_pack(__ldg(Minv + m0 * Ndim + kg),
                        __ldg(Minv + m0 * Ndim + kg + 1),
                        afr_h[mt][kt][0], afr_l[mt][kt][0]);
            split2_pack(__ldg(Minv + (m0 + 8) * Ndim + kg),
                        __ldg(Minv + (m0 + 8) * Ndim + kg + 1),
                        afr_h[mt][kt][1], afr_l[mt][kt][1]);
            split2_pack(__ldg(Minv + m0 * Ndim + kg + 8),
                        __ldg(Minv + m0 * Ndim + kg + 9),
                        afr_h[mt][kt][2], afr_l[mt][kt][2]);
            split2_pack(__ldg(Minv + (m0 + 8) * Ndim + kg + 8),
                        __ldg(Minv + (m0 + 8) * Ndim + kg + 9),
                        afr_h[mt][kt][3], afr_l[mt][kt][3]);
        }
    }

    // ---- per-thread state: local tile rows, cols n0,n0+1 ----
    const int jl0 = 16 * warp + rsub;
    const int gr0 = 128 * (int)rank + jl0;
    float atb[4], uv[4], tp[4];
#pragma unroll
    for (int i = 0; i < 4; i++) {
        const int grow = gr0 + ((i >> 1) ? 8 : 0);
        atb[i] = real ? __ldg(Atb + grow * Kdim + c0 + n0 + (i & 1)) : 0.f;
        uv[i] = 0.f; tp[i] = 0.f;
    }
    int woff[4];
#pragma unroll
    for (int i = 0; i < 4; i++)
        woff[i] = (n0 + (i & 1)) * WSTRIDE + jl0 + ((i >> 1) ? 8 : 0);
    __syncthreads();   // zero-fill done before initial w stores
#pragma unroll
    for (int i = 0; i < 4; i++) {     // initial w = Atb into buffer 0
        const u16 h = bfb(atb[i]);
        const u16 l = bfb(atb[i] - bff(h));
        wsm[woff[i]]        = h;
        wsm[WLEV + woff[i]] = l;
    }

    // B-frag base offsets (u32 index into wsm): w[col=rsub][k0=2kq]
    const int bbase = (rsub * WSTRIDE + 2 * kq) >> 1;  // u32 units
    const u32* wsm32 = (const u32*)wsm;

    // exchange plumbing
    const u32 peer = 1u - rank;
    const u32 peer_wx = mapa_peer(smem_u32(&wxbar), peer);
    u32 my_pb[2], peer_pb[2];
#pragma unroll
    for (int p = 0; p < 2; p++) {
        my_pb[p]   = smem_u32(&pbuf[p][tid]);
        peer_pb[p] = mapa_peer(my_pb[p], peer);
    }

    __syncthreads();
    asm volatile("barrier.cluster.arrive.aligned;" ::: "memory");
    asm volatile("barrier.cluster.wait.aligned;"   ::: "memory");

    // ---------------- main loop ----------------
    for (int it = 0; it < ITERS; ++it) {
        const u32 par = (u32)(it & 1);
        const int rb = (it & 1) * (WBUF >> 1);   // read-buffer u32 offset
        __syncthreads();   // prev iter's w stores (other buffer) visible

        float acc0[4] = {0.f, 0.f, 0.f, 0.f};
        float acc1[4] = {0.f, 0.f, 0.f, 0.f};
        const u32* wh = wsm32 + rb + bbase;
        const u32* wl = wh + (WLEV >> 1);
#pragma unroll
        for (int kt = 0; kt < 8; kt++) {
            const u32 bh0 = wh[8 * kt], bh1 = wh[8 * kt + 4];
            const u32 bl0 = wl[8 * kt], bl1 = wl[8 * kt + 4];
            mma16816(acc0, afr_h[0][kt], bh0, bh1);   // hh
            mma16816(acc1, afr_h[1][kt], bh0, bh1);
            mma16816(acc0, afr_h[0][kt], bl0, bl1);   // hl
            mma16816(acc1, afr_h[1][kt], bl0, bl1);
            mma16816(acc0, afr_l[0][kt], bh0, bh1);   // lh
            mma16816(acc1, afr_l[1][kt], bh0, bh1);
            mma16816(acc0, afr_l[0][kt], bl0, bl1);   // ll
            mma16816(acc1, afr_l[1][kt], bl0, bl1);
        }

        // ship the peer-owned tile (mt = 1-rank), keep local (mt = rank)
        const float* sendq = rank ? acc0 : acc1;
        const float* keepq = rank ? acc1 : acc0;
        asm volatile("st.shared::cluster.v4.b32 [%0], {%1,%2,%3,%4};"
                     :: "r"(peer_pb[par]),
                        "r"(__float_as_uint(sendq[0])), "r"(__float_as_uint(sendq[1])),
                        "r"(__float_as_uint(sendq[2])), "r"(__float_as_uint(sendq[3]))
                     : "memory");
        // cluster-scope release (R14 fix): remote pbuf store visible to the
        // peer's cluster-scope acquire wait.
        asm volatile("mbarrier.arrive.release.cluster.shared::cluster.b64 _, [%0];"
                     :: "r"(peer_wx) : "memory");
        BAR_WAIT_CL(smem_u32(&wxbar), par);

        float4 pr;
        asm volatile("ld.shared.v4.f32 {%0,%1,%2,%3}, [%4];"
                     : "=f"(pr.x), "=f"(pr.y), "=f"(pr.z), "=f"(pr.w)
                     : "r"(my_pb[par]));
        tp[0] = keepq[0] + pr.x;
        tp[1] = keepq[1] + pr.y;
        tp[2] = keepq[2] + pr.z;
        tp[3] = keepq[3] + pr.w;

        // z/u update + 2-level w split/store into the OTHER buffer
        u16* wdst = wsm + ((it & 1) ^ 1) * WBUF;
#pragma unroll
        for (int i = 0; i < 4; i++) {
            const float g = tp[i] + uv[i];
            float zn = fmaxf(g - tau, 0.f) + fminf(g + tau, 0.f);
            zn = fminf(fmaxf(zn, 0.f), 1.f);
            uv[i] += tp[i] - zn;
            const float w = fmaf(rho, zn - uv[i], atb[i]);
            const u16 h = bfb(w);
            const u16 l = bfb(w - bff(h));
            wdst[woff[i]]        = h;
            wdst[WLEV + woff[i]] = l;
        }
    }

    if (real) {
#pragma unroll
        for (int i = 0; i < 4; i++) {
            const int grow = gr0 + ((i >> 1) ? 8 : 0);
            out[grow * Kdim + c0 + n0 + (i & 1)] = tp[i];
        }
    }
    asm volatile("barrier.cluster.arrive.aligned;" ::: "memory");
    asm volatile("barrier.cluster.wait.aligned;"   ::: "memory");
}

// ---------------------------------------------------------------------------
extern "C" void kernel_launch(void* const* d_in, const int* in_sizes, int n_in,
                              void* d_out, int out_size)
{
    // metadata order: T, s_A, s_mic_data, rho_param, lam_param
    const float* s_A   = (const float*)d_in[1];
    const float* s_mic = (const float*)d_in[2];
    const float* rho_p = (const float*)d_in[3];
    const float* lam_p = (const float*)d_in[4];
    float* out = (float*)d_out;

    float *G, *Atb, *X0, *X1, *Y, *ap;
    cudaGetSymbolAddress((void**)&G,   g_G);
    cudaGetSymbolAddress((void**)&Atb, g_Atb);
    cudaGetSymbolAddress((void**)&X0,  g_X0);
    cudaGetSymbolAddress((void**)&X1,  g_X1);
    cudaGetSymbolAddress((void**)&Y,   g_Y);
    cudaGetSymbolAddress((void**)&ap,  g_a);

    cudaMemsetAsync(G,   0, Ndim * Ndim * sizeof(float));
    cudaMemsetAsync(Atb, 0, Ndim * Kdim * sizeof(float));
    dim3 tb(32, 32);
    dim3 gbz(8, 8, 4);
    atx_kernel<<<gbz, tb>>>(s_A, s_A,   G,   rho_p, 1);
    atx_kernel<<<gbz, tb>>>(s_A, s_mic, Atb, rho_p, 0);

    // Newton-Schulz inverse (fp32): X <- 2X - X@(G@X)
    norm_kernel<<<1, 256>>>(G, ap);
    init_x_kernel<<<256, 256>>>(X0, ap);
    dim3 gb(8, 8);
    float* Xc = X0; float* Xn = X1;
    for (int i = 0; i < NS_ITERS; i++) {
        gemm256_kernel<<<gb, tb>>>(G,  Xc, Y,  0);
        gemm256_kernel<<<gb, tb>>>(Xc, Y,  Xn, 1);
        float* t = Xc; Xc = Xn; Xn = t;
    }

    admm_mma_kernel<<<128, 256>>>(Xc, Atb, rho_p, lam_p, out);
}